// round 6
// baseline (speedup 1.0000x reference)
#include <cuda_runtime.h>
#include <cuda_bf16.h>
#include <cstdint>

// Problem constants
#define BB 2
#define TT 2048
#define DD 1024
#define HH 16
#define HD 64
#define M_ROWS (BB * TT)        // 4096
#define QKV_N (3 * DD)          // 3072
#define KDIM 1024

// Scratch (allocation-free rule: __device__ globals)
__device__ float g_qkv[(size_t)M_ROWS * QKV_N]; // [B,T,3D]
__device__ float g_z[(size_t)M_ROWS * DD];      // [B,T,D]

// ===========================================================================
// bf16 3-pass split GEMM NT via mma.sync (baseline PTX, no arch-a features):
//   C[M,N] = A[M,K] * B[N,K]^T, fp32 in/out, K=1024.
// Split x = hi + lo (bf16 each); C = Ah*Bh + Ah*Bl + Al*Bh.
// CTA tile 128x128, K-chunk 32, 256 threads = 8 warps (2 m-strips x 4 n-strips),
// warp tile 64x32, mma.m16n8k16 fragments loaded as packed b32 from smem.
// smem arrays [128][40] bf16 (stride 40 => conflict-free fragment LDS).
// ===========================================================================
#define SSTR 40
#define CK 32
#define NCHUNK (KDIM / CK)

__device__ __forceinline__ void mma_bf16(float* d, uint32_t a0, uint32_t a1,
                                         uint32_t a2, uint32_t a3,
                                         uint32_t b0, uint32_t b1)
{
    asm volatile(
        "mma.sync.aligned.m16n8k16.row.col.f32.bf16.bf16.f32 "
        "{%0,%1,%2,%3}, {%4,%5,%6,%7}, {%8,%9}, {%0,%1,%2,%3};"
        : "+f"(d[0]), "+f"(d[1]), "+f"(d[2]), "+f"(d[3])
        : "r"(a0), "r"(a1), "r"(a2), "r"(a3), "r"(b0), "r"(b1));
}

// Convert a float4 into packed hi (2x b32) and lo (2x b32) bf16 pairs.
__device__ __forceinline__ void split4(float4 v, uint32_t* hi, uint32_t* lo)
{
    __nv_bfloat16 hx = __float2bfloat16_rn(v.x);
    __nv_bfloat16 hy = __float2bfloat16_rn(v.y);
    __nv_bfloat16 hz = __float2bfloat16_rn(v.z);
    __nv_bfloat16 hw = __float2bfloat16_rn(v.w);
    __nv_bfloat16 lx = __float2bfloat16_rn(v.x - __bfloat162float(hx));
    __nv_bfloat16 ly = __float2bfloat16_rn(v.y - __bfloat162float(hy));
    __nv_bfloat16 lz = __float2bfloat16_rn(v.z - __bfloat162float(hz));
    __nv_bfloat16 lw = __float2bfloat16_rn(v.w - __bfloat162float(hw));
    __nv_bfloat162 h01; h01.x = hx; h01.y = hy;
    __nv_bfloat162 h23; h23.x = hz; h23.y = hw;
    __nv_bfloat162 l01; l01.x = lx; l01.y = ly;
    __nv_bfloat162 l23; l23.x = lz; l23.y = lw;
    hi[0] = *(uint32_t*)&h01; hi[1] = *(uint32_t*)&h23;
    lo[0] = *(uint32_t*)&l01; lo[1] = *(uint32_t*)&l23;
}

__global__ __launch_bounds__(256) void gemm_bf16x3(const float* __restrict__ A,
                                                   const float* __restrict__ B,
                                                   float* __restrict__ C,
                                                   int N)
{
    __shared__ __nv_bfloat16 Ah[128 * SSTR];
    __shared__ __nv_bfloat16 Al[128 * SSTR];
    __shared__ __nv_bfloat16 Bh[128 * SSTR];
    __shared__ __nv_bfloat16 Bl[128 * SSTR];

    const int tid = threadIdx.x;
    const int wid = tid >> 5;
    const int lid = tid & 31;
    const int g   = lid >> 2;      // group 0..7
    const int tig = lid & 3;       // thread-in-group 0..3
    const int wm  = wid & 1;       // m strip (0/1) of 64
    const int wn  = wid >> 1;      // n strip (0..3) of 32

    const float* Ab = A + (size_t)blockIdx.y * 128 * KDIM;
    const float* Bb = B + (size_t)blockIdx.x * 128 * KDIM;

    // loader mapping: 4 float4 per thread per matrix per chunk
    const int lrow = tid >> 1;               // used as (f>>3) with f=tid+256*i
    float acc[4][4][4];
#pragma unroll
    for (int mi = 0; mi < 4; mi++)
#pragma unroll
        for (int ni = 0; ni < 4; ni++)
#pragma unroll
            for (int r = 0; r < 4; r++) acc[mi][ni][r] = 0.f;

    float4 pa[4], pb[4];
    // prefetch chunk 0
#pragma unroll
    for (int i = 0; i < 4; i++) {
        const int f = tid + 256 * i;
        const int row = f >> 3;
        const int kq = f & 7;
        pa[i] = *(const float4*)(Ab + (size_t)row * KDIM + kq * 4);
        pb[i] = *(const float4*)(Bb + (size_t)row * KDIM + kq * 4);
    }

    for (int c = 0; c < NCHUNK; c++) {
        // store prefetched chunk into smem with hi/lo split
#pragma unroll
        for (int i = 0; i < 4; i++) {
            const int f = tid + 256 * i;
            const int row = f >> 3;
            const int kq = f & 7;
            uint32_t hi[2], lo[2];
            split4(pa[i], hi, lo);
            *(uint32_t*)&Ah[row * SSTR + kq * 4]     = hi[0];
            *(uint32_t*)&Ah[row * SSTR + kq * 4 + 2] = hi[1];
            *(uint32_t*)&Al[row * SSTR + kq * 4]     = lo[0];
            *(uint32_t*)&Al[row * SSTR + kq * 4 + 2] = lo[1];
            split4(pb[i], hi, lo);
            *(uint32_t*)&Bh[row * SSTR + kq * 4]     = hi[0];
            *(uint32_t*)&Bh[row * SSTR + kq * 4 + 2] = hi[1];
            *(uint32_t*)&Bl[row * SSTR + kq * 4]     = lo[0];
            *(uint32_t*)&Bl[row * SSTR + kq * 4 + 2] = lo[1];
        }
        __syncthreads();

        // prefetch next chunk while computing
        if (c + 1 < NCHUNK) {
#pragma unroll
            for (int i = 0; i < 4; i++) {
                const int f = tid + 256 * i;
                const int row = f >> 3;
                const int kq = f & 7;
                pa[i] = *(const float4*)(Ab + (size_t)row * KDIM + (c + 1) * CK + kq * 4);
                pb[i] = *(const float4*)(Bb + (size_t)row * KDIM + (c + 1) * CK + kq * 4);
            }
        }

        // compute: 2 k16 groups x 3 passes x (4m x 4n) mma
#pragma unroll
        for (int k16 = 0; k16 < 2; k16++) {
#pragma unroll
            for (int p = 0; p < 3; p++) {
                const __nv_bfloat16* As_ = (p < 2) ? Ah : Al;
                const __nv_bfloat16* Bs_ = (p == 1) ? Bl : Bh;
                const int kk = k16 * 16 + tig * 2;

                uint32_t bf[4][2];
#pragma unroll
                for (int ni = 0; ni < 4; ni++) {
                    const int n = wn * 32 + ni * 8 + g;
                    bf[ni][0] = *(const uint32_t*)&Bs_[n * SSTR + kk];
                    bf[ni][1] = *(const uint32_t*)&Bs_[n * SSTR + kk + 8];
                }
#pragma unroll
                for (int mi = 0; mi < 4; mi++) {
                    const int r = wm * 64 + mi * 16 + g;
                    uint32_t a0 = *(const uint32_t*)&As_[r * SSTR + kk];
                    uint32_t a1 = *(const uint32_t*)&As_[(r + 8) * SSTR + kk];
                    uint32_t a2 = *(const uint32_t*)&As_[r * SSTR + kk + 8];
                    uint32_t a3 = *(const uint32_t*)&As_[(r + 8) * SSTR + kk + 8];
#pragma unroll
                    for (int ni = 0; ni < 4; ni++)
                        mma_bf16(acc[mi][ni], a0, a1, a2, a3, bf[ni][0], bf[ni][1]);
                }
            }
        }
        __syncthreads();
    }
    (void)lrow;

    // epilogue: c0,c1 at (row g, col tig*2), c2,c3 at (row g+8)
#pragma unroll
    for (int mi = 0; mi < 4; mi++) {
        const int r0 = blockIdx.y * 128 + wm * 64 + mi * 16 + g;
#pragma unroll
        for (int ni = 0; ni < 4; ni++) {
            const int c0 = blockIdx.x * 128 + wn * 32 + ni * 8 + tig * 2;
            float2 v0; v0.x = acc[mi][ni][0]; v0.y = acc[mi][ni][1];
            float2 v1; v1.x = acc[mi][ni][2]; v1.y = acc[mi][ni][3];
            *(float2*)(C + (size_t)r0 * N + c0)       = v0;
            *(float2*)(C + (size_t)(r0 + 8) * N + c0) = v1;
        }
    }
}

// ---------------------------------------------------------------------------
// Flash attention, fp32, causal (unchanged from passing round-0 kernel).
// ---------------------------------------------------------------------------
#define QS_STR 65
#define PS_STR 68
#define FLASH_SMEM ((2 * 64 * QS_STR + 64 * PS_STR) * 4)

__global__ __launch_bounds__(256) void flash_attn(const float* __restrict__ qkv,
                                                  float* __restrict__ z)
{
    extern __shared__ float sm[];
    float* Qs  = sm;                    // [64][65]
    float* KVs = sm + 64 * QS_STR;      // [64][65]
    float* Ps  = sm + 2 * 64 * QS_STR;  // [64][68]

    const int qt = blockIdx.x;
    const int h  = blockIdx.y;
    const int b  = blockIdx.z;
    const int tid = threadIdx.x;
    const int rg = tid >> 4;
    const int cg = tid & 15;
    const int lr = tid >> 2;
    const int lc = (tid & 3) * 16;
    const int q0 = qt * 64;
    const size_t rs = QKV_N;

    {
        const float* src = qkv + ((size_t)(b * TT + q0 + lr)) * rs + h * HD + lc;
#pragma unroll
        for (int i = 0; i < 4; i++) {
            float4 v = *(const float4*)(src + i * 4);
            float* d = &Qs[lr * QS_STR + lc + i * 4];
            d[0] = v.x * 0.125f; d[1] = v.y * 0.125f;
            d[2] = v.z * 0.125f; d[3] = v.w * 0.125f;
        }
    }

    float m_[4], l_[4], o_[4][4];
#pragma unroll
    for (int i = 0; i < 4; i++) {
        m_[i] = -1e30f; l_[i] = 0.f;
#pragma unroll
        for (int c = 0; c < 4; c++) o_[i][c] = 0.f;
    }

    for (int kt = 0; kt <= qt; kt++) {
        const int k0 = kt * 64;
        __syncthreads();
        {
            const float* src = qkv + ((size_t)(b * TT + k0 + lr)) * rs + DD + h * HD + lc;
#pragma unroll
            for (int i = 0; i < 4; i++) {
                float4 v = *(const float4*)(src + i * 4);
                float* d = &KVs[lr * QS_STR + lc + i * 4];
                d[0] = v.x; d[1] = v.y; d[2] = v.z; d[3] = v.w;
            }
        }
        __syncthreads();

        float s[4][4];
#pragma unroll
        for (int i = 0; i < 4; i++)
#pragma unroll
            for (int j = 0; j < 4; j++) s[i][j] = 0.f;

#pragma unroll 4
        for (int d = 0; d < 64; d++) {
            float qa[4], kb[4];
#pragma unroll
            for (int i = 0; i < 4; i++) qa[i] = Qs[(rg * 4 + i) * QS_STR + d];
#pragma unroll
            for (int j = 0; j < 4; j++) kb[j] = KVs[(cg + 16 * j) * QS_STR + d];
#pragma unroll
            for (int i = 0; i < 4; i++)
#pragma unroll
                for (int j = 0; j < 4; j++) s[i][j] += qa[i] * kb[j];
        }

        if (kt == qt) {
#pragma unroll
            for (int i = 0; i < 4; i++)
#pragma unroll
                for (int j = 0; j < 4; j++)
                    if (cg + 16 * j > rg * 4 + i) s[i][j] = -1e30f;
        }

#pragma unroll
        for (int i = 0; i < 4; i++) {
            float mx = fmaxf(fmaxf(s[i][0], s[i][1]), fmaxf(s[i][2], s[i][3]));
#pragma unroll
            for (int off = 1; off < 16; off <<= 1)
                mx = fmaxf(mx, __shfl_xor_sync(0xffffffffu, mx, off));
            float mnew = fmaxf(m_[i], mx);
            float alpha = __expf(m_[i] - mnew);
            float psum = 0.f;
#pragma unroll
            for (int j = 0; j < 4; j++) {
                float p = __expf(s[i][j] - mnew);
                s[i][j] = p;
                psum += p;
            }
#pragma unroll
            for (int off = 1; off < 16; off <<= 1)
                psum += __shfl_xor_sync(0xffffffffu, psum, off);
            l_[i] = l_[i] * alpha + psum;
            m_[i] = mnew;
#pragma unroll
            for (int c = 0; c < 4; c++) o_[i][c] *= alpha;
#pragma unroll
            for (int j = 0; j < 4; j++)
                Ps[(rg * 4 + i) * PS_STR + cg + 16 * j] = s[i][j];
        }
        __syncthreads();

        {
            const float* src = qkv + ((size_t)(b * TT + k0 + lr)) * rs + 2 * DD + h * HD + lc;
#pragma unroll
            for (int i = 0; i < 4; i++) {
                float4 v = *(const float4*)(src + i * 4);
                float* d = &KVs[lr * QS_STR + lc + i * 4];
                d[0] = v.x; d[1] = v.y; d[2] = v.z; d[3] = v.w;
            }
        }
        __syncthreads();

#pragma unroll 4
        for (int j = 0; j < 64; j++) {
            float pa[4], vb[4];
#pragma unroll
            for (int i = 0; i < 4; i++) pa[i] = Ps[(rg * 4 + i) * PS_STR + j];
#pragma unroll
            for (int c = 0; c < 4; c++) vb[c] = KVs[j * QS_STR + cg + 16 * c];
#pragma unroll
            for (int i = 0; i < 4; i++)
#pragma unroll
                for (int c = 0; c < 4; c++) o_[i][c] += pa[i] * vb[c];
        }
    }

#pragma unroll
    for (int i = 0; i < 4; i++) {
        float inv_l = 1.f / l_[i];
        size_t row = (size_t)(b * TT + q0 + rg * 4 + i) * DD + h * HD;
#pragma unroll
        for (int c = 0; c < 4; c++)
            z[row + cg + 16 * c] = o_[i][c] * inv_l;
    }
}

// ---------------------------------------------------------------------------
extern "C" void kernel_launch(void* const* d_in, const int* in_sizes, int n_in,
                              void* d_out, int out_size)
{
    const float* X    = (const float*)d_in[0];
    const float* Wqkv = (const float*)d_in[1];
    const float* Wout = (const float*)d_in[2];
    float* out = (float*)d_out;

    float* qkv; float* z;
    cudaGetSymbolAddress((void**)&qkv, g_qkv);
    cudaGetSymbolAddress((void**)&z, g_z);

    cudaFuncSetAttribute(flash_attn, cudaFuncAttributeMaxDynamicSharedMemorySize,
                         FLASH_SMEM);

    // 1) qkv = X @ W_qkv^T : [4096,1024] x [3072,1024]^T  (bf16x3 mma.sync)
    gemm_bf16x3<<<dim3(QKV_N / 128, M_ROWS / 128), 256>>>(X, Wqkv, qkv, QKV_N);
    // 2) causal flash attention -> z
    flash_attn<<<dim3(TT / 64, HH, BB), 256, FLASH_SMEM>>>(qkv, z);
    // 3) out = z @ W_out^T : [4096,1024] x [1024,1024]^T  (bf16x3 mma.sync)
    gemm_bf16x3<<<dim3(DD / 128, M_ROWS / 128), 256>>>(z, Wout, out, DD);
}

// round 7
// speedup vs baseline: 2.6592x; 2.6592x over previous
#include <cuda_runtime.h>
#include <cuda_bf16.h>
#include <cstdint>

// Problem constants
#define BB 2
#define TT 2048
#define DD 1024
#define HH 16
#define HD 64
#define M_ROWS (BB * TT)        // 4096
#define QKV_N (3 * DD)          // 3072
#define KDIM 1024

// Scratch (allocation-free rule: __device__ globals)
__device__ float g_qkv[(size_t)M_ROWS * QKV_N]; // [B,T,3D]
__device__ float g_z[(size_t)M_ROWS * DD];      // [B,T,D]

// ===========================================================================
// Shared mma.sync helpers (baseline PTX, assembles on plain sm_103 target)
// ===========================================================================
__device__ __forceinline__ void mma_bf16(float* d, uint32_t a0, uint32_t a1,
                                         uint32_t a2, uint32_t a3,
                                         uint32_t b0, uint32_t b1)
{
    asm volatile(
        "mma.sync.aligned.m16n8k16.row.col.f32.bf16.bf16.f32 "
        "{%0,%1,%2,%3}, {%4,%5,%6,%7}, {%8,%9}, {%0,%1,%2,%3};"
        : "+f"(d[0]), "+f"(d[1]), "+f"(d[2]), "+f"(d[3])
        : "r"(a0), "r"(a1), "r"(a2), "r"(a3), "r"(b0), "r"(b1));
}

// Convert a float4 into packed hi (2x b32) and lo (2x b32) bf16 pairs.
__device__ __forceinline__ void split4(float4 v, uint32_t* hi, uint32_t* lo)
{
    __nv_bfloat16 hx = __float2bfloat16_rn(v.x);
    __nv_bfloat16 hy = __float2bfloat16_rn(v.y);
    __nv_bfloat16 hz = __float2bfloat16_rn(v.z);
    __nv_bfloat16 hw = __float2bfloat16_rn(v.w);
    __nv_bfloat16 lx = __float2bfloat16_rn(v.x - __bfloat162float(hx));
    __nv_bfloat16 ly = __float2bfloat16_rn(v.y - __bfloat162float(hy));
    __nv_bfloat16 lz = __float2bfloat16_rn(v.z - __bfloat162float(hz));
    __nv_bfloat16 lw = __float2bfloat16_rn(v.w - __bfloat162float(hw));
    __nv_bfloat162 h01; h01.x = hx; h01.y = hy;
    __nv_bfloat162 h23; h23.x = hz; h23.y = hw;
    __nv_bfloat162 l01; l01.x = lx; l01.y = ly;
    __nv_bfloat162 l23; l23.x = lz; l23.y = lw;
    hi[0] = *(uint32_t*)&h01; hi[1] = *(uint32_t*)&h23;
    lo[0] = *(uint32_t*)&l01; lo[1] = *(uint32_t*)&l23;
}

// Pack two fp32 into bf16x2 hi + bf16x2 lo residual.
__device__ __forceinline__ void splitp(float x, float y, uint32_t& hi, uint32_t& lo)
{
    __nv_bfloat16 hx = __float2bfloat16_rn(x);
    __nv_bfloat16 hy = __float2bfloat16_rn(y);
    __nv_bfloat16 lx = __float2bfloat16_rn(x - __bfloat162float(hx));
    __nv_bfloat16 ly = __float2bfloat16_rn(y - __bfloat162float(hy));
    __nv_bfloat162 hh; hh.x = hx; hh.y = hy;
    __nv_bfloat162 ll; ll.x = lx; ll.y = ly;
    hi = *(uint32_t*)&hh; lo = *(uint32_t*)&ll;
}

// ===========================================================================
// bf16 3-pass split GEMM NT (unchanged from passing round-6 kernel)
// ===========================================================================
#define SSTR 40
#define CK 32
#define NCHUNK (KDIM / CK)

__global__ __launch_bounds__(256) void gemm_bf16x3(const float* __restrict__ A,
                                                   const float* __restrict__ B,
                                                   float* __restrict__ C,
                                                   int N)
{
    __shared__ __nv_bfloat16 Ah[128 * SSTR];
    __shared__ __nv_bfloat16 Al[128 * SSTR];
    __shared__ __nv_bfloat16 Bh[128 * SSTR];
    __shared__ __nv_bfloat16 Bl[128 * SSTR];

    const int tid = threadIdx.x;
    const int wid = tid >> 5;
    const int lid = tid & 31;
    const int g   = lid >> 2;
    const int tig = lid & 3;
    const int wm  = wid & 1;
    const int wn  = wid >> 1;

    const float* Ab = A + (size_t)blockIdx.y * 128 * KDIM;
    const float* Bb = B + (size_t)blockIdx.x * 128 * KDIM;

    float acc[4][4][4];
#pragma unroll
    for (int mi = 0; mi < 4; mi++)
#pragma unroll
        for (int ni = 0; ni < 4; ni++)
#pragma unroll
            for (int r = 0; r < 4; r++) acc[mi][ni][r] = 0.f;

    float4 pa[4], pb[4];
#pragma unroll
    for (int i = 0; i < 4; i++) {
        const int f = tid + 256 * i;
        const int row = f >> 3;
        const int kq = f & 7;
        pa[i] = *(const float4*)(Ab + (size_t)row * KDIM + kq * 4);
        pb[i] = *(const float4*)(Bb + (size_t)row * KDIM + kq * 4);
    }

    for (int c = 0; c < NCHUNK; c++) {
#pragma unroll
        for (int i = 0; i < 4; i++) {
            const int f = tid + 256 * i;
            const int row = f >> 3;
            const int kq = f & 7;
            uint32_t hi[2], lo[2];
            split4(pa[i], hi, lo);
            *(uint32_t*)&Ah[row * SSTR + kq * 4]     = hi[0];
            *(uint32_t*)&Ah[row * SSTR + kq * 4 + 2] = hi[1];
            *(uint32_t*)&Al[row * SSTR + kq * 4]     = lo[0];
            *(uint32_t*)&Al[row * SSTR + kq * 4 + 2] = lo[1];
            split4(pb[i], hi, lo);
            *(uint32_t*)&Bh[row * SSTR + kq * 4]     = hi[0];
            *(uint32_t*)&Bh[row * SSTR + kq * 4 + 2] = hi[1];
            *(uint32_t*)&Bl[row * SSTR + kq * 4]     = lo[0];
            *(uint32_t*)&Bl[row * SSTR + kq * 4 + 2] = lo[1];
        }
        __syncthreads();

        if (c + 1 < NCHUNK) {
#pragma unroll
            for (int i = 0; i < 4; i++) {
                const int f = tid + 256 * i;
                const int row = f >> 3;
                const int kq = f & 7;
                pa[i] = *(const float4*)(Ab + (size_t)row * KDIM + (c + 1) * CK + kq * 4);
                pb[i] = *(const float4*)(Bb + (size_t)row * KDIM + (c + 1) * CK + kq * 4);
            }
        }

#pragma unroll
        for (int k16 = 0; k16 < 2; k16++) {
#pragma unroll
            for (int p = 0; p < 3; p++) {
                const __nv_bfloat16* As_ = (p < 2) ? Ah : Al;
                const __nv_bfloat16* Bs_ = (p == 1) ? Bl : Bh;
                const int kk = k16 * 16 + tig * 2;

                uint32_t bf[4][2];
#pragma unroll
                for (int ni = 0; ni < 4; ni++) {
                    const int n = wn * 32 + ni * 8 + g;
                    bf[ni][0] = *(const uint32_t*)&Bs_[n * SSTR + kk];
                    bf[ni][1] = *(const uint32_t*)&Bs_[n * SSTR + kk + 8];
                }
#pragma unroll
                for (int mi = 0; mi < 4; mi++) {
                    const int r = wm * 64 + mi * 16 + g;
                    uint32_t a0 = *(const uint32_t*)&As_[r * SSTR + kk];
                    uint32_t a1 = *(const uint32_t*)&As_[(r + 8) * SSTR + kk];
                    uint32_t a2 = *(const uint32_t*)&As_[r * SSTR + kk + 8];
                    uint32_t a3 = *(const uint32_t*)&As_[(r + 8) * SSTR + kk + 8];
#pragma unroll
                    for (int ni = 0; ni < 4; ni++)
                        mma_bf16(acc[mi][ni], a0, a1, a2, a3, bf[ni][0], bf[ni][1]);
                }
            }
        }
        __syncthreads();
    }

#pragma unroll
    for (int mi = 0; mi < 4; mi++) {
        const int r0 = blockIdx.y * 128 + wm * 64 + mi * 16 + g;
#pragma unroll
        for (int ni = 0; ni < 4; ni++) {
            const int c0 = blockIdx.x * 128 + wn * 32 + ni * 8 + tig * 2;
            float2 v0; v0.x = acc[mi][ni][0]; v0.y = acc[mi][ni][1];
            float2 v1; v1.x = acc[mi][ni][2]; v1.y = acc[mi][ni][3];
            *(float2*)(C + (size_t)r0 * N + c0)       = v0;
            *(float2*)(C + (size_t)(r0 + 8) * N + c0) = v1;
        }
    }
}

// ===========================================================================
// Flash attention with mma.sync bf16 (3-pass split for S=QK^T and O=PV).
// CTA: 128 q-rows of one (b,h). 8 warps, warp w owns rows [16w,16w+16).
// KV tiles of 64. P kept in registers (C-frag -> A-frag repack).
// smem bf16: Qh/Ql[128][72], Kh/Kl[64][72] ([kv][hd]), Vh/Vl[64][72] ([hd][kv]).
// stride 72 -> conflict-free fragment LDS (bank = (4g+tig) mod 32).
// ===========================================================================
#define FQ 128
#define FKV 64
#define FSTR 72
#define FLASH_SMEM ((2 * 128 * FSTR + 4 * 64 * FSTR) * 2)   // 73728 B

__global__ __launch_bounds__(256) void flash_mma(const float* __restrict__ qkv,
                                                 float* __restrict__ z)
{
    extern __shared__ __nv_bfloat16 fsm[];
    __nv_bfloat16* Qh = fsm;
    __nv_bfloat16* Ql = Qh + 128 * FSTR;
    __nv_bfloat16* Kh = Ql + 128 * FSTR;
    __nv_bfloat16* Kl = Kh + 64 * FSTR;
    __nv_bfloat16* Vh = Kl + 64 * FSTR;   // transposed: [hd][kv]
    __nv_bfloat16* Vl = Vh + 64 * FSTR;

    const int qt = blockIdx.x;
    const int h  = blockIdx.y;
    const int b  = blockIdx.z;
    const int tid = threadIdx.x;
    const int wid = tid >> 5;
    const int lid = tid & 31;
    const int g   = lid >> 2;
    const int tig = lid & 3;
    const int q0  = qt * FQ;
    const size_t rs = QKV_N;

    // Load Q once: scale by 1/8, split hi/lo
#pragma unroll
    for (int j = 0; j < 8; j++) {
        const int i = tid + 256 * j;     // float4 index 0..2047
        const int row = i >> 4;          // 0..127
        const int hq = i & 15;           // float4 within row
        float4 v = *(const float4*)(qkv + (size_t)(b * TT + q0 + row) * rs + h * HD + hq * 4);
        v.x *= 0.125f; v.y *= 0.125f; v.z *= 0.125f; v.w *= 0.125f;
        uint32_t hi[2], lo[2];
        split4(v, hi, lo);
        *(uint2*)&Qh[row * FSTR + hq * 4] = make_uint2(hi[0], hi[1]);
        *(uint2*)&Ql[row * FSTR + hq * 4] = make_uint2(lo[0], lo[1]);
    }

    float m_[2], l_[2], o_[8][4];
    m_[0] = m_[1] = -1e30f;
    l_[0] = l_[1] = 0.f;
#pragma unroll
    for (int ni = 0; ni < 8; ni++)
#pragma unroll
        for (int e = 0; e < 4; e++) o_[ni][e] = 0.f;

    const int qwmin = q0 + wid * 16;     // first q row of this warp's strip
    const int nkv = 2 * qt + 2;

    for (int kt = 0; kt < nkv; kt++) {
        __syncthreads();    // previous tile's smem reads done
        // Load K tile [kv][hd] and V tile transposed [hd][kv]
#pragma unroll
        for (int j = 0; j < 4; j++) {
            const int i = tid + 256 * j;
            const int row = i >> 4;      // kv 0..63
            const int hq = i & 15;
            const size_t base = (size_t)(b * TT + kt * FKV + row) * rs + h * HD + hq * 4;
            float4 kv4 = *(const float4*)(qkv + base + DD);
            uint32_t hi[2], lo[2];
            split4(kv4, hi, lo);
            *(uint2*)&Kh[row * FSTR + hq * 4] = make_uint2(hi[0], hi[1]);
            *(uint2*)&Kl[row * FSTR + hq * 4] = make_uint2(lo[0], lo[1]);

            float4 vv = *(const float4*)(qkv + base + 2 * DD);
            const float vf[4] = {vv.x, vv.y, vv.z, vv.w};
#pragma unroll
            for (int e = 0; e < 4; e++) {
                __nv_bfloat16 hb = __float2bfloat16_rn(vf[e]);
                __nv_bfloat16 lb = __float2bfloat16_rn(vf[e] - __bfloat162float(hb));
                Vh[(hq * 4 + e) * FSTR + row] = hb;
                Vl[(hq * 4 + e) * FSTR + row] = lb;
            }
        }
        __syncthreads();

        // Warp strip fully masked by causality?  (all kv > all q of strip)
        if (kt * FKV > qwmin + 15) continue;

        // ---- S = Q K^T (3-pass), per-warp 16x64 tile ----
        float s[8][4];
#pragma unroll
        for (int ni = 0; ni < 8; ni++)
#pragma unroll
            for (int e = 0; e < 4; e++) s[ni][e] = 0.f;

#pragma unroll
        for (int k16 = 0; k16 < 4; k16++) {
            const int kk = k16 * 16 + tig * 2;
            const int r = wid * 16 + g;
            uint32_t ah0 = *(const uint32_t*)&Qh[r * FSTR + kk];
            uint32_t ah1 = *(const uint32_t*)&Qh[(r + 8) * FSTR + kk];
            uint32_t ah2 = *(const uint32_t*)&Qh[r * FSTR + kk + 8];
            uint32_t ah3 = *(const uint32_t*)&Qh[(r + 8) * FSTR + kk + 8];
            uint32_t al0 = *(const uint32_t*)&Ql[r * FSTR + kk];
            uint32_t al1 = *(const uint32_t*)&Ql[(r + 8) * FSTR + kk];
            uint32_t al2 = *(const uint32_t*)&Ql[r * FSTR + kk + 8];
            uint32_t al3 = *(const uint32_t*)&Ql[(r + 8) * FSTR + kk + 8];
#pragma unroll
            for (int ni = 0; ni < 8; ni++) {
                const int n = ni * 8 + g;
                uint32_t bh0 = *(const uint32_t*)&Kh[n * FSTR + kk];
                uint32_t bh1 = *(const uint32_t*)&Kh[n * FSTR + kk + 8];
                uint32_t bl0 = *(const uint32_t*)&Kl[n * FSTR + kk];
                uint32_t bl1 = *(const uint32_t*)&Kl[n * FSTR + kk + 8];
                mma_bf16(s[ni], ah0, ah1, ah2, ah3, bh0, bh1);
                mma_bf16(s[ni], ah0, ah1, ah2, ah3, bl0, bl1);
                mma_bf16(s[ni], al0, al1, al2, al3, bh0, bh1);
            }
        }

        // Causal mask (only on diagonal-overlap tiles)
        if (kt * FKV + FKV - 1 > qwmin) {
#pragma unroll
            for (int ni = 0; ni < 8; ni++) {
#pragma unroll
                for (int e = 0; e < 4; e++) {
                    const int qr = qwmin + g + ((e >= 2) ? 8 : 0);
                    const int kc = kt * FKV + ni * 8 + tig * 2 + (e & 1);
                    if (kc > qr) s[ni][e] = -1e30f;
                }
            }
        }

        // ---- online softmax (rows g and g+8 of the strip) ----
        float mx0 = s[0][0], mx1 = s[0][2];
#pragma unroll
        for (int ni = 0; ni < 8; ni++) {
            mx0 = fmaxf(mx0, fmaxf(s[ni][0], s[ni][1]));
            mx1 = fmaxf(mx1, fmaxf(s[ni][2], s[ni][3]));
        }
        mx0 = fmaxf(mx0, __shfl_xor_sync(0xffffffffu, mx0, 1));
        mx0 = fmaxf(mx0, __shfl_xor_sync(0xffffffffu, mx0, 2));
        mx1 = fmaxf(mx1, __shfl_xor_sync(0xffffffffu, mx1, 1));
        mx1 = fmaxf(mx1, __shfl_xor_sync(0xffffffffu, mx1, 2));

        const float mn0 = fmaxf(m_[0], mx0);
        const float mn1 = fmaxf(m_[1], mx1);
        const float alpha0 = __expf(m_[0] - mn0);
        const float alpha1 = __expf(m_[1] - mn1);

        float ps0 = 0.f, ps1 = 0.f;
#pragma unroll
        for (int ni = 0; ni < 8; ni++) {
            s[ni][0] = __expf(s[ni][0] - mn0); ps0 += s[ni][0];
            s[ni][1] = __expf(s[ni][1] - mn0); ps0 += s[ni][1];
            s[ni][2] = __expf(s[ni][2] - mn1); ps1 += s[ni][2];
            s[ni][3] = __expf(s[ni][3] - mn1); ps1 += s[ni][3];
        }
        ps0 += __shfl_xor_sync(0xffffffffu, ps0, 1);
        ps0 += __shfl_xor_sync(0xffffffffu, ps0, 2);
        ps1 += __shfl_xor_sync(0xffffffffu, ps1, 1);
        ps1 += __shfl_xor_sync(0xffffffffu, ps1, 2);

        l_[0] = l_[0] * alpha0 + ps0;
        l_[1] = l_[1] * alpha1 + ps1;
        m_[0] = mn0; m_[1] = mn1;
#pragma unroll
        for (int ni = 0; ni < 8; ni++) {
            o_[ni][0] *= alpha0; o_[ni][1] *= alpha0;
            o_[ni][2] *= alpha1; o_[ni][3] *= alpha1;
        }

        // ---- O += P V (3-pass); P repacked C-frag -> A-frag in registers ----
#pragma unroll
        for (int k16 = 0; k16 < 4; k16++) {
            const int n0 = 2 * k16, n1 = 2 * k16 + 1;
            uint32_t ph0, ph1, ph2, ph3, pl0, pl1, pl2, pl3;
            splitp(s[n0][0], s[n0][1], ph0, pl0);
            splitp(s[n0][2], s[n0][3], ph1, pl1);
            splitp(s[n1][0], s[n1][1], ph2, pl2);
            splitp(s[n1][2], s[n1][3], ph3, pl3);
            const int kk = k16 * 16 + tig * 2;
#pragma unroll
            for (int ni = 0; ni < 8; ni++) {
                const int n = ni * 8 + g;     // hd index
                uint32_t bh0 = *(const uint32_t*)&Vh[n * FSTR + kk];
                uint32_t bh1 = *(const uint32_t*)&Vh[n * FSTR + kk + 8];
                uint32_t bl0 = *(const uint32_t*)&Vl[n * FSTR + kk];
                uint32_t bl1 = *(const uint32_t*)&Vl[n * FSTR + kk + 8];
                mma_bf16(o_[ni], ph0, ph1, ph2, ph3, bh0, bh1);
                mma_bf16(o_[ni], ph0, ph1, ph2, ph3, bl0, bl1);
                mma_bf16(o_[ni], pl0, pl1, pl2, pl3, bh0, bh1);
            }
        }
    }

    // Epilogue: normalize, write z[b, q, h*64 + hd]
    const float il0 = 1.f / l_[0];
    const float il1 = 1.f / l_[1];
    const size_t r0 = (size_t)(b * TT + q0 + wid * 16 + g);
#pragma unroll
    for (int ni = 0; ni < 8; ni++) {
        const int col = h * HD + ni * 8 + tig * 2;
        float2 v0; v0.x = o_[ni][0] * il0; v0.y = o_[ni][1] * il0;
        float2 v1; v1.x = o_[ni][2] * il1; v1.y = o_[ni][3] * il1;
        *(float2*)(z + r0 * DD + col)       = v0;
        *(float2*)(z + (r0 + 8) * DD + col) = v1;
    }
}

// ---------------------------------------------------------------------------
extern "C" void kernel_launch(void* const* d_in, const int* in_sizes, int n_in,
                              void* d_out, int out_size)
{
    const float* X    = (const float*)d_in[0];
    const float* Wqkv = (const float*)d_in[1];
    const float* Wout = (const float*)d_in[2];
    float* out = (float*)d_out;

    float* qkv; float* z;
    cudaGetSymbolAddress((void**)&qkv, g_qkv);
    cudaGetSymbolAddress((void**)&z, g_z);

    cudaFuncSetAttribute(flash_mma, cudaFuncAttributeMaxDynamicSharedMemorySize,
                         FLASH_SMEM);

    // 1) qkv = X @ W_qkv^T  (bf16x3 mma.sync)
    gemm_bf16x3<<<dim3(QKV_N / 128, M_ROWS / 128), 256>>>(X, Wqkv, qkv, QKV_N);
    // 2) causal flash attention -> z  (bf16x3 mma.sync)
    flash_mma<<<dim3(TT / FQ, HH, BB), 256, FLASH_SMEM>>>(qkv, z);
    // 3) out = z @ W_out^T  (bf16x3 mma.sync)
    gemm_bf16x3<<<dim3(DD / 128, M_ROWS / 128), 256>>>(z, Wout, out, DD);
}

// round 8
// speedup vs baseline: 3.2568x; 1.2247x over previous
#include <cuda_runtime.h>
#include <cuda_bf16.h>
#include <cstdint>

// Problem constants
#define BB 2
#define TT 2048
#define DD 1024
#define HH 16
#define HD 64
#define M_ROWS 4096
#define QKV_N 3072
#define KDIM 1024

typedef __nv_bfloat16 bf16;

// ---------------------------------------------------------------------------
// Device-global scratch (allocation-free rule)
// ---------------------------------------------------------------------------
__device__ bf16 g_Xh[(size_t)M_ROWS * KDIM];
__device__ bf16 g_Xl[(size_t)M_ROWS * KDIM];
__device__ bf16 g_Wqh[(size_t)QKV_N * KDIM];
__device__ bf16 g_Wql[(size_t)QKV_N * KDIM];
__device__ bf16 g_Woh[(size_t)DD * DD];
__device__ bf16 g_Wol[(size_t)DD * DD];
__device__ bf16 g_qh[(size_t)M_ROWS * QKV_N];
__device__ bf16 g_ql[(size_t)M_ROWS * QKV_N];
__device__ bf16 g_zh[(size_t)M_ROWS * DD];
__device__ bf16 g_zl[(size_t)M_ROWS * DD];

// ---------------------------------------------------------------------------
// PTX helpers (baseline ISA: mma.sync sm_80, ldmatrix sm_75, cp.async sm_80)
// ---------------------------------------------------------------------------
__device__ __forceinline__ uint32_t smem_u32(const void* p) {
    uint32_t a;
    asm("{ .reg .u64 t; cvta.to.shared.u64 t, %1; cvt.u32.u64 %0, t; }"
        : "=r"(a) : "l"(p));
    return a;
}

__device__ __forceinline__ void cp16(uint32_t dst, const void* src) {
    asm volatile("cp.async.cg.shared.global [%0], [%1], 16;"
                 :: "r"(dst), "l"(src));
}
#define CP_COMMIT() asm volatile("cp.async.commit_group;" ::: "memory")
#define CP_WAIT1()  asm volatile("cp.async.wait_group 1;" ::: "memory")
#define CP_WAIT0()  asm volatile("cp.async.wait_group 0;" ::: "memory")

__device__ __forceinline__ void ldsm4(uint32_t& r0, uint32_t& r1, uint32_t& r2,
                                      uint32_t& r3, uint32_t addr) {
    asm volatile("ldmatrix.sync.aligned.m8n8.x4.shared.b16 {%0,%1,%2,%3}, [%4];"
                 : "=r"(r0), "=r"(r1), "=r"(r2), "=r"(r3) : "r"(addr));
}
__device__ __forceinline__ void ldsm4t(uint32_t& r0, uint32_t& r1, uint32_t& r2,
                                       uint32_t& r3, uint32_t addr) {
    asm volatile("ldmatrix.sync.aligned.m8n8.x4.trans.shared.b16 {%0,%1,%2,%3}, [%4];"
                 : "=r"(r0), "=r"(r1), "=r"(r2), "=r"(r3) : "r"(addr));
}

__device__ __forceinline__ void mma_bf16(float* d, uint32_t a0, uint32_t a1,
                                         uint32_t a2, uint32_t a3,
                                         uint32_t b0, uint32_t b1)
{
    asm volatile(
        "mma.sync.aligned.m16n8k16.row.col.f32.bf16.bf16.f32 "
        "{%0,%1,%2,%3}, {%4,%5,%6,%7}, {%8,%9}, {%0,%1,%2,%3};"
        : "+f"(d[0]), "+f"(d[1]), "+f"(d[2]), "+f"(d[3])
        : "r"(a0), "r"(a1), "r"(a2), "r"(a3), "r"(b0), "r"(b1));
}

__device__ __forceinline__ void split4(float4 v, uint32_t* hi, uint32_t* lo)
{
    __nv_bfloat16 hx = __float2bfloat16_rn(v.x);
    __nv_bfloat16 hy = __float2bfloat16_rn(v.y);
    __nv_bfloat16 hz = __float2bfloat16_rn(v.z);
    __nv_bfloat16 hw = __float2bfloat16_rn(v.w);
    __nv_bfloat16 lx = __float2bfloat16_rn(v.x - __bfloat162float(hx));
    __nv_bfloat16 ly = __float2bfloat16_rn(v.y - __bfloat162float(hy));
    __nv_bfloat16 lz = __float2bfloat16_rn(v.z - __bfloat162float(hz));
    __nv_bfloat16 lw = __float2bfloat16_rn(v.w - __bfloat162float(hw));
    __nv_bfloat162 h01; h01.x = hx; h01.y = hy;
    __nv_bfloat162 h23; h23.x = hz; h23.y = hw;
    __nv_bfloat162 l01; l01.x = lx; l01.y = ly;
    __nv_bfloat162 l23; l23.x = lz; l23.y = lw;
    hi[0] = *(uint32_t*)&h01; hi[1] = *(uint32_t*)&h23;
    lo[0] = *(uint32_t*)&l01; lo[1] = *(uint32_t*)&l23;
}

__device__ __forceinline__ void splitp(float x, float y, uint32_t& hi, uint32_t& lo)
{
    __nv_bfloat16 hx = __float2bfloat16_rn(x);
    __nv_bfloat16 hy = __float2bfloat16_rn(y);
    __nv_bfloat16 lx = __float2bfloat16_rn(x - __bfloat162float(hx));
    __nv_bfloat16 ly = __float2bfloat16_rn(y - __bfloat162float(hy));
    __nv_bfloat162 hh; hh.x = hx; hh.y = hy;
    __nv_bfloat162 ll; ll.x = lx; ll.y = ly;
    hi = *(uint32_t*)&hh; lo = *(uint32_t*)&ll;
}

// ---------------------------------------------------------------------------
// Conversion kernel: fp32 -> bf16 hi + bf16 lo residual
// ---------------------------------------------------------------------------
__global__ void convert_split(const float* __restrict__ src,
                              bf16* __restrict__ hi, bf16* __restrict__ lo,
                              int n4)
{
    int i = blockIdx.x * blockDim.x + threadIdx.x;
    if (i >= n4) return;
    float4 v = ((const float4*)src)[i];
    uint32_t h[2], l[2];
    split4(v, h, l);
    ((uint2*)hi)[i] = make_uint2(h[0], h[1]);
    ((uint2*)lo)[i] = make_uint2(l[0], l[1]);
}

// ===========================================================================
// GEMM NT on pre-converted bf16 hi/lo:  C = A * B^T, K=1024.
// 3-pass split: Ah*Bh + Ah*Bl + Al*Bh. CTA tile 128x128, K-chunk 32,
// 2-stage cp.async pipeline, ldmatrix fragments, 2 CTAs/SM.
// smem per stage: Ah,Al,Bh,Bl [128][40] bf16 (80B row stride, conflict-free).
// SPLIT=true: write Ch/Cl bf16 pair; else write Cf fp32.
// ===========================================================================
#define G_STR 40
#define G_ARR 10240                  // 128*40*2
#define G_STAGE (4 * G_ARR)          // 40960
#define G_SMEM (2 * G_STAGE)         // 81920
#define NCHUNK (KDIM / 32)

template<bool SPLIT>
__global__ __launch_bounds__(256, 2) void gemm_pc(
    const bf16* __restrict__ Agh, const bf16* __restrict__ Agl,
    const bf16* __restrict__ Bgh, const bf16* __restrict__ Bgl,
    float* __restrict__ Cf, bf16* __restrict__ Ch, bf16* __restrict__ Cl,
    int N)
{
    extern __shared__ char gsm[];
    const uint32_t sb0 = smem_u32(gsm);

    const int tid = threadIdx.x;
    const int wid = tid >> 5;
    const int lid = tid & 31;
    const int g   = lid >> 2;
    const int tig = lid & 3;
    const int wm  = wid & 1;
    const int wn  = wid >> 1;
    const int bY  = blockIdx.y * 128;
    const int bX  = blockIdx.x * 128;

    // ldmatrix lane address components
    const uint32_t aOff = (uint32_t)(wm * 64 + (lid & 15)) * 80
                        + ((lid & 16) ? 16u : 0u);
    const uint32_t bOff = (uint32_t)(wn * 32 + (lid & 7) + ((lid & 16) ? 8 : 0)) * 80
                        + ((lid & 8) ? 16u : 0u);

    // loader: chunk c -> stage st
    const int ldRow = tid >> 2;
    const int ldCh  = tid & 3;
#define G_LOAD(c, st) do {                                                     \
        const uint32_t sb_ = sb0 + (st) * G_STAGE;                             \
        _Pragma("unroll")                                                      \
        for (int j_ = 0; j_ < 2; j_++) {                                       \
            const int row_ = ldRow + 64 * j_;                                  \
            const uint32_t d_ = (uint32_t)row_ * 80 + ldCh * 16;               \
            const size_t ao_ = (size_t)(bY + row_) * KDIM + (c) * 32 + ldCh * 8;\
            const size_t bo_ = (size_t)(bX + row_) * KDIM + (c) * 32 + ldCh * 8;\
            cp16(sb_ + d_,             Agh + ao_);                             \
            cp16(sb_ + G_ARR + d_,     Agl + ao_);                             \
            cp16(sb_ + 2 * G_ARR + d_, Bgh + bo_);                             \
            cp16(sb_ + 3 * G_ARR + d_, Bgl + bo_);                             \
        }                                                                      \
    } while (0)

    float acc[4][4][4];
#pragma unroll
    for (int mi = 0; mi < 4; mi++)
#pragma unroll
        for (int ni = 0; ni < 4; ni++)
#pragma unroll
            for (int r = 0; r < 4; r++) acc[mi][ni][r] = 0.f;

    G_LOAD(0, 0); CP_COMMIT();
    G_LOAD(1, 1); CP_COMMIT();

    for (int c = 0; c < NCHUNK; c++) {
        if (c + 1 < NCHUNK) { CP_WAIT1(); } else { CP_WAIT0(); }
        __syncthreads();

        const uint32_t sb = sb0 + (c & 1) * G_STAGE;
#pragma unroll
        for (int k16 = 0; k16 < 2; k16++) {
            const uint32_t kb = k16 * 32;    // 16 elems = 32 bytes
#pragma unroll
            for (int p = 0; p < 3; p++) {
                const uint32_t aBase = sb + ((p < 2) ? 0 : G_ARR) + aOff + kb;
                const uint32_t bBase = sb + ((p == 1) ? 3 * G_ARR : 2 * G_ARR)
                                       + bOff + kb;
                uint32_t bf_[2][4];
                ldsm4(bf_[0][0], bf_[0][1], bf_[0][2], bf_[0][3], bBase);
                ldsm4(bf_[1][0], bf_[1][1], bf_[1][2], bf_[1][3], bBase + 16 * 80);
#pragma unroll
                for (int mi = 0; mi < 4; mi++) {
                    uint32_t a0, a1, a2, a3;
                    ldsm4(a0, a1, a2, a3, aBase + (uint32_t)mi * 16 * 80);
#pragma unroll
                    for (int ni = 0; ni < 4; ni++)
                        mma_bf16(acc[mi][ni], a0, a1, a2, a3,
                                 bf_[ni >> 1][(ni & 1) * 2],
                                 bf_[ni >> 1][(ni & 1) * 2 + 1]);
                }
            }
        }
        __syncthreads();
        if (c + 2 < NCHUNK) { G_LOAD(c + 2, (c & 1)); CP_COMMIT(); }
    }

    // epilogue
#pragma unroll
    for (int mi = 0; mi < 4; mi++) {
        const int r0 = bY + wm * 64 + mi * 16 + g;
#pragma unroll
        for (int ni = 0; ni < 4; ni++) {
            const int c0 = bX + wn * 32 + ni * 8 + tig * 2;
            if (SPLIT) {
                uint32_t hp, lp;
                splitp(acc[mi][ni][0], acc[mi][ni][1], hp, lp);
                *(uint32_t*)&Ch[(size_t)r0 * N + c0] = hp;
                *(uint32_t*)&Cl[(size_t)r0 * N + c0] = lp;
                splitp(acc[mi][ni][2], acc[mi][ni][3], hp, lp);
                *(uint32_t*)&Ch[(size_t)(r0 + 8) * N + c0] = hp;
                *(uint32_t*)&Cl[(size_t)(r0 + 8) * N + c0] = lp;
            } else {
                float2 v0; v0.x = acc[mi][ni][0]; v0.y = acc[mi][ni][1];
                float2 v1; v1.x = acc[mi][ni][2]; v1.y = acc[mi][ni][3];
                *(float2*)(Cf + (size_t)r0 * N + c0)       = v0;
                *(float2*)(Cf + (size_t)(r0 + 8) * N + c0) = v1;
            }
        }
    }
#undef G_LOAD
}

// ===========================================================================
// Flash attention on pre-converted qkv hi/lo, mma.sync bf16 3-pass.
// CTA: 128 q-rows of one (b,h); 8 warps, warp strip = 16 rows. KV tiles 64.
// cp.async 2-stage KV pipeline; V natural [kv][hd], PV B-frags via
// ldmatrix.trans; S scaled by 1/8 post-mma; z written as bf16 hi/lo.
// smem: Qh/Ql [128][72] + 2 stages x (Kh,Kl,Vh,Vl [64][72]) = 110592 B.
// ===========================================================================
#define F_STR 72
#define F_QARR 18432                 // 128*72*2
#define F_KARR 9216                  // 64*72*2
#define F_STAGE (4 * F_KARR)         // 36864
#define F_SMEM (2 * F_QARR + 2 * F_STAGE)   // 110592

__global__ __launch_bounds__(256, 1) void flash_pc(
    const bf16* __restrict__ qh, const bf16* __restrict__ ql,
    bf16* __restrict__ zh, bf16* __restrict__ zl)
{
    extern __shared__ char fsmc[];
    const uint32_t sb  = smem_u32(fsmc);
    const uint32_t sQh = sb;
    const uint32_t sQl = sb + F_QARR;
    const uint32_t sKV = sb + 2 * F_QARR;

    const int qt  = (TT / 128 - 1) - blockIdx.x;   // heavy tiles first
    const int h   = blockIdx.y;
    const int b   = blockIdx.z;
    const int tid = threadIdx.x;
    const int wid = tid >> 5;
    const int lid = tid & 31;
    const int g   = lid >> 2;
    const int tig = lid & 3;
    const int q0  = qt * 128;
    const int nkv = 2 * qt + 2;
    const int qwmin = q0 + wid * 16;

    // Q cp.async (group 0, together with KV tile 0)
#pragma unroll
    for (int j = 0; j < 4; j++) {
        const int idx = tid + 256 * j;        // 0..1023
        const int row = idx >> 3;
        const int ch  = idx & 7;
        const size_t off = (size_t)(b * TT + q0 + row) * QKV_N + h * HD + ch * 8;
        const uint32_t d = (uint32_t)row * 144 + ch * 16;
        cp16(sQh + d, qh + off);
        cp16(sQl + d, ql + off);
    }

#define F_LOADKV(kt, st) do {                                                  \
        const uint32_t kb_ = sKV + (st) * F_STAGE;                             \
        _Pragma("unroll")                                                      \
        for (int j_ = 0; j_ < 2; j_++) {                                       \
            const int idx_ = tid + 256 * j_;                                   \
            const int row_ = idx_ >> 3;                                        \
            const int ch_  = idx_ & 7;                                         \
            const size_t base_ = (size_t)(b * TT + (kt) * 64 + row_) * QKV_N   \
                               + h * HD + ch_ * 8;                             \
            const uint32_t d_ = (uint32_t)row_ * 144 + ch_ * 16;               \
            cp16(kb_ + d_,             qh + base_ + DD);                       \
            cp16(kb_ + F_KARR + d_,    ql + base_ + DD);                       \
            cp16(kb_ + 2 * F_KARR + d_, qh + base_ + 2 * DD);                  \
            cp16(kb_ + 3 * F_KARR + d_, ql + base_ + 2 * DD);                  \
        }                                                                      \
    } while (0)

    F_LOADKV(0, 0); CP_COMMIT();
    F_LOADKV(1, 1); CP_COMMIT();

    // lane address components
    const uint32_t qOff = (uint32_t)(wid * 16 + (lid & 15)) * 144
                        + ((lid & 16) ? 16u : 0u);
    const uint32_t kOff = (uint32_t)((lid & 7) + ((lid & 16) ? 8 : 0)) * 144
                        + ((lid & 8) ? 16u : 0u);
    const uint32_t vRow = (uint32_t)((lid & 7) + ((lid & 8) ? 8 : 0)) * 144
                        + ((lid & 16) ? 16u : 0u);

    float m_[2], l_[2], o_[8][4];
    m_[0] = m_[1] = -1e30f;
    l_[0] = l_[1] = 0.f;
#pragma unroll
    for (int ni = 0; ni < 8; ni++)
#pragma unroll
        for (int e = 0; e < 4; e++) o_[ni][e] = 0.f;

    for (int kt = 0; kt < nkv; kt++) {
        if (kt + 1 < nkv) { CP_WAIT1(); } else { CP_WAIT0(); }
        __syncthreads();

        const uint32_t st = sKV + (kt & 1) * F_STAGE;
        const uint32_t sKh = st, sKl = st + F_KARR;
        const uint32_t sVh = st + 2 * F_KARR, sVl = st + 3 * F_KARR;

        if (kt * 64 <= qwmin + 15) {
            // ---- S = Q K^T (3-pass) ----
            float s[8][4];
#pragma unroll
            for (int ni = 0; ni < 8; ni++)
#pragma unroll
                for (int e = 0; e < 4; e++) s[ni][e] = 0.f;

#pragma unroll
            for (int k16 = 0; k16 < 4; k16++) {
                const uint32_t kb = k16 * 32;
                uint32_t qh0, qh1, qh2, qh3, ql0, ql1, ql2, ql3;
                ldsm4(qh0, qh1, qh2, qh3, sQh + qOff + kb);
                ldsm4(ql0, ql1, ql2, ql3, sQl + qOff + kb);
                uint32_t bh[4][4], bl[4][4];
#pragma unroll
                for (int nh = 0; nh < 4; nh++) {
                    const uint32_t ro = (uint32_t)nh * 16 * 144;
                    ldsm4(bh[nh][0], bh[nh][1], bh[nh][2], bh[nh][3],
                          sKh + kOff + ro + kb);
                    ldsm4(bl[nh][0], bl[nh][1], bl[nh][2], bl[nh][3],
                          sKl + kOff + ro + kb);
                }
#pragma unroll
                for (int ni = 0; ni < 8; ni++) {
                    const int nh = ni >> 1, rs = (ni & 1) * 2;
                    mma_bf16(s[ni], qh0, qh1, qh2, qh3, bh[nh][rs], bh[nh][rs + 1]);
                    mma_bf16(s[ni], qh0, qh1, qh2, qh3, bl[nh][rs], bl[nh][rs + 1]);
                    mma_bf16(s[ni], ql0, ql1, ql2, ql3, bh[nh][rs], bh[nh][rs + 1]);
                }
            }

            // scale 1/sqrt(HD)
#pragma unroll
            for (int ni = 0; ni < 8; ni++)
#pragma unroll
                for (int e = 0; e < 4; e++) s[ni][e] *= 0.125f;

            // causal mask on diagonal-overlap tiles
            if (kt * 64 + 63 > qwmin) {
#pragma unroll
                for (int ni = 0; ni < 8; ni++)
#pragma unroll
                    for (int e = 0; e < 4; e++) {
                        const int qr = qwmin + g + ((e >= 2) ? 8 : 0);
                        const int kc = kt * 64 + ni * 8 + tig * 2 + (e & 1);
                        if (kc > qr) s[ni][e] = -1e30f;
                    }
            }

            // ---- online softmax ----
            float mx0 = s[0][0], mx1 = s[0][2];
#pragma unroll
            for (int ni = 0; ni < 8; ni++) {
                mx0 = fmaxf(mx0, fmaxf(s[ni][0], s[ni][1]));
                mx1 = fmaxf(mx1, fmaxf(s[ni][2], s[ni][3]));
            }
            mx0 = fmaxf(mx0, __shfl_xor_sync(0xffffffffu, mx0, 1));
            mx0 = fmaxf(mx0, __shfl_xor_sync(0xffffffffu, mx0, 2));
            mx1 = fmaxf(mx1, __shfl_xor_sync(0xffffffffu, mx1, 1));
            mx1 = fmaxf(mx1, __shfl_xor_sync(0xffffffffu, mx1, 2));

            const float mn0 = fmaxf(m_[0], mx0);
            const float mn1 = fmaxf(m_[1], mx1);
            const float al0 = __expf(m_[0] - mn0);
            const float al1 = __expf(m_[1] - mn1);

            float ps0 = 0.f, ps1 = 0.f;
#pragma unroll
            for (int ni = 0; ni < 8; ni++) {
                s[ni][0] = __expf(s[ni][0] - mn0); ps0 += s[ni][0];
                s[ni][1] = __expf(s[ni][1] - mn0); ps0 += s[ni][1];
                s[ni][2] = __expf(s[ni][2] - mn1); ps1 += s[ni][2];
                s[ni][3] = __expf(s[ni][3] - mn1); ps1 += s[ni][3];
            }
            ps0 += __shfl_xor_sync(0xffffffffu, ps0, 1);
            ps0 += __shfl_xor_sync(0xffffffffu, ps0, 2);
            ps1 += __shfl_xor_sync(0xffffffffu, ps1, 1);
            ps1 += __shfl_xor_sync(0xffffffffu, ps1, 2);

            l_[0] = l_[0] * al0 + ps0;
            l_[1] = l_[1] * al1 + ps1;
            m_[0] = mn0; m_[1] = mn1;
#pragma unroll
            for (int ni = 0; ni < 8; ni++) {
                o_[ni][0] *= al0; o_[ni][1] *= al0;
                o_[ni][2] *= al1; o_[ni][3] *= al1;
            }

            // ---- O += P V (3-pass); B-frags via ldmatrix.trans ----
#pragma unroll
            for (int k16 = 0; k16 < 4; k16++) {
                const int n0 = 2 * k16, n1 = 2 * k16 + 1;
                uint32_t ph0, ph1, ph2, ph3, pl0, pl1, pl2, pl3;
                splitp(s[n0][0], s[n0][1], ph0, pl0);
                splitp(s[n0][2], s[n0][3], ph1, pl1);
                splitp(s[n1][0], s[n1][1], ph2, pl2);
                splitp(s[n1][2], s[n1][3], ph3, pl3);

                const uint32_t rb = (uint32_t)k16 * 16 * 144;   // kv row block
                uint32_t vh[4][4], vl[4][4];
#pragma unroll
                for (int nh = 0; nh < 4; nh++) {
                    const uint32_t co = (uint32_t)nh * 32;      // hd col bytes
                    ldsm4t(vh[nh][0], vh[nh][1], vh[nh][2], vh[nh][3],
                           sVh + vRow + rb + co);
                    ldsm4t(vl[nh][0], vl[nh][1], vl[nh][2], vl[nh][3],
                           sVl + vRow + rb + co);
                }
#pragma unroll
                for (int ni = 0; ni < 8; ni++) {
                    const int nh = ni >> 1, rs = (ni & 1) * 2;
                    mma_bf16(o_[ni], ph0, ph1, ph2, ph3, vh[nh][rs], vh[nh][rs + 1]);
                    mma_bf16(o_[ni], ph0, ph1, ph2, ph3, vl[nh][rs], vl[nh][rs + 1]);
                    mma_bf16(o_[ni], pl0, pl1, pl2, pl3, vh[nh][rs], vh[nh][rs + 1]);
                }
            }
        }

        __syncthreads();
        if (kt + 2 < nkv) { F_LOADKV(kt + 2, (kt & 1)); CP_COMMIT(); }
    }

    // epilogue: normalize, write z hi/lo
    const float il0 = 1.f / l_[0];
    const float il1 = 1.f / l_[1];
    const size_t r0 = (size_t)(b * TT + q0 + wid * 16 + g);
#pragma unroll
    for (int ni = 0; ni < 8; ni++) {
        const int col = h * HD + ni * 8 + tig * 2;
        uint32_t hp, lp;
        splitp(o_[ni][0] * il0, o_[ni][1] * il0, hp, lp);
        *(uint32_t*)&zh[r0 * DD + col] = hp;
        *(uint32_t*)&zl[r0 * DD + col] = lp;
        splitp(o_[ni][2] * il1, o_[ni][3] * il1, hp, lp);
        *(uint32_t*)&zh[(r0 + 8) * DD + col] = hp;
        *(uint32_t*)&zl[(r0 + 8) * DD + col] = lp;
    }
#undef F_LOADKV
}

// ---------------------------------------------------------------------------
extern "C" void kernel_launch(void* const* d_in, const int* in_sizes, int n_in,
                              void* d_out, int out_size)
{
    const float* X    = (const float*)d_in[0];
    const float* Wqkv = (const float*)d_in[1];
    const float* Wout = (const float*)d_in[2];
    float* out = (float*)d_out;

    bf16 *Xh, *Xl, *Wqh, *Wql, *Woh, *Wol, *qh, *ql, *zh, *zl;
    cudaGetSymbolAddress((void**)&Xh,  g_Xh);
    cudaGetSymbolAddress((void**)&Xl,  g_Xl);
    cudaGetSymbolAddress((void**)&Wqh, g_Wqh);
    cudaGetSymbolAddress((void**)&Wql, g_Wql);
    cudaGetSymbolAddress((void**)&Woh, g_Woh);
    cudaGetSymbolAddress((void**)&Wol, g_Wol);
    cudaGetSymbolAddress((void**)&qh,  g_qh);
    cudaGetSymbolAddress((void**)&ql,  g_ql);
    cudaGetSymbolAddress((void**)&zh,  g_zh);
    cudaGetSymbolAddress((void**)&zl,  g_zl);

    cudaFuncSetAttribute(gemm_pc<true>,
                         cudaFuncAttributeMaxDynamicSharedMemorySize, G_SMEM);
    cudaFuncSetAttribute(gemm_pc<false>,
                         cudaFuncAttributeMaxDynamicSharedMemorySize, G_SMEM);
    cudaFuncSetAttribute(flash_pc,
                         cudaFuncAttributeMaxDynamicSharedMemorySize, F_SMEM);

    // 0) split inputs to bf16 hi/lo
    convert_split<<<M_ROWS * KDIM / 1024, 256>>>(X, Xh, Xl, M_ROWS * KDIM / 4);
    convert_split<<<QKV_N * KDIM / 1024, 256>>>(Wqkv, Wqh, Wql, QKV_N * KDIM / 4);
    convert_split<<<DD * DD / 1024, 256>>>(Wout, Woh, Wol, DD * DD / 4);

    // 1) qkv = X @ Wqkv^T  -> hi/lo bf16
    gemm_pc<true><<<dim3(QKV_N / 128, M_ROWS / 128), 256, G_SMEM>>>(
        Xh, Xl, Wqh, Wql, nullptr, qh, ql, QKV_N);

    // 2) causal flash attention -> z hi/lo
    flash_pc<<<dim3(TT / 128, HH, BB), 256, F_SMEM>>>(qh, ql, zh, zl);

    // 3) out = z @ Wout^T -> fp32
    gemm_pc<false><<<dim3(DD / 128, M_ROWS / 128), 256, G_SMEM>>>(
        zh, zl, Woh, Wol, out, nullptr, nullptr, DD);
}

// round 9
// speedup vs baseline: 4.0333x; 1.2384x over previous
#include <cuda_runtime.h>
#include <cuda_bf16.h>
#include <cuda_fp16.h>
#include <cstdint>

// Problem constants
#define BB 2
#define TT 2048
#define DD 1024
#define HH 16
#define HD 64
#define M_ROWS 4096
#define QKV_N 3072
#define KDIM 1024

typedef __nv_bfloat16 bf16;

// ---------------------------------------------------------------------------
// Device-global scratch (allocation-free rule)
// ---------------------------------------------------------------------------
__device__ bf16  g_Xh[(size_t)M_ROWS * KDIM];
__device__ bf16  g_Xl[(size_t)M_ROWS * KDIM];
__device__ bf16  g_Wqh[(size_t)QKV_N * KDIM];
__device__ bf16  g_Wql[(size_t)QKV_N * KDIM];
__device__ __half g_Wo16[(size_t)DD * DD];
__device__ bf16  g_qh[(size_t)M_ROWS * QKV_N];   // q,k cols 0..2047 used
__device__ bf16  g_ql[(size_t)M_ROWS * QKV_N];
__device__ __half g_v16[(size_t)M_ROWS * DD];    // v as fp16
__device__ __half g_z16[(size_t)M_ROWS * DD];    // z as fp16

// ---------------------------------------------------------------------------
// PTX helpers (baseline ISA: mma.sync sm_80, ldmatrix sm_75, cp.async sm_80)
// ---------------------------------------------------------------------------
__device__ __forceinline__ uint32_t smem_u32(const void* p) {
    uint32_t a;
    asm("{ .reg .u64 t; cvta.to.shared.u64 t, %1; cvt.u32.u64 %0, t; }"
        : "=r"(a) : "l"(p));
    return a;
}

__device__ __forceinline__ void cp16(uint32_t dst, const void* src) {
    asm volatile("cp.async.cg.shared.global [%0], [%1], 16;"
                 :: "r"(dst), "l"(src));
}
#define CP_COMMIT() asm volatile("cp.async.commit_group;" ::: "memory")
#define CP_WAIT1()  asm volatile("cp.async.wait_group 1;" ::: "memory")
#define CP_WAIT0()  asm volatile("cp.async.wait_group 0;" ::: "memory")

__device__ __forceinline__ void ldsm4(uint32_t& r0, uint32_t& r1, uint32_t& r2,
                                      uint32_t& r3, uint32_t addr) {
    asm volatile("ldmatrix.sync.aligned.m8n8.x4.shared.b16 {%0,%1,%2,%3}, [%4];"
                 : "=r"(r0), "=r"(r1), "=r"(r2), "=r"(r3) : "r"(addr));
}
__device__ __forceinline__ void ldsm4t(uint32_t& r0, uint32_t& r1, uint32_t& r2,
                                       uint32_t& r3, uint32_t addr) {
    asm volatile("ldmatrix.sync.aligned.m8n8.x4.trans.shared.b16 {%0,%1,%2,%3}, [%4];"
                 : "=r"(r0), "=r"(r1), "=r"(r2), "=r"(r3) : "r"(addr));
}

__device__ __forceinline__ void mma_bf16(float* d, uint32_t a0, uint32_t a1,
                                         uint32_t a2, uint32_t a3,
                                         uint32_t b0, uint32_t b1)
{
    asm volatile(
        "mma.sync.aligned.m16n8k16.row.col.f32.bf16.bf16.f32 "
        "{%0,%1,%2,%3}, {%4,%5,%6,%7}, {%8,%9}, {%0,%1,%2,%3};"
        : "+f"(d[0]), "+f"(d[1]), "+f"(d[2]), "+f"(d[3])
        : "r"(a0), "r"(a1), "r"(a2), "r"(a3), "r"(b0), "r"(b1));
}

__device__ __forceinline__ void mma_f16(float* d, uint32_t a0, uint32_t a1,
                                        uint32_t a2, uint32_t a3,
                                        uint32_t b0, uint32_t b1)
{
    asm volatile(
        "mma.sync.aligned.m16n8k16.row.col.f32.f16.f16.f32 "
        "{%0,%1,%2,%3}, {%4,%5,%6,%7}, {%8,%9}, {%0,%1,%2,%3};"
        : "+f"(d[0]), "+f"(d[1]), "+f"(d[2]), "+f"(d[3])
        : "r"(a0), "r"(a1), "r"(a2), "r"(a3), "r"(b0), "r"(b1));
}

__device__ __forceinline__ void split4(float4 v, uint32_t* hi, uint32_t* lo)
{
    __nv_bfloat16 hx = __float2bfloat16_rn(v.x);
    __nv_bfloat16 hy = __float2bfloat16_rn(v.y);
    __nv_bfloat16 hz = __float2bfloat16_rn(v.z);
    __nv_bfloat16 hw = __float2bfloat16_rn(v.w);
    __nv_bfloat16 lx = __float2bfloat16_rn(v.x - __bfloat162float(hx));
    __nv_bfloat16 ly = __float2bfloat16_rn(v.y - __bfloat162float(hy));
    __nv_bfloat16 lz = __float2bfloat16_rn(v.z - __bfloat162float(hz));
    __nv_bfloat16 lw = __float2bfloat16_rn(v.w - __bfloat162float(hw));
    __nv_bfloat162 h01; h01.x = hx; h01.y = hy;
    __nv_bfloat162 h23; h23.x = hz; h23.y = hw;
    __nv_bfloat162 l01; l01.x = lx; l01.y = ly;
    __nv_bfloat162 l23; l23.x = lz; l23.y = lw;
    hi[0] = *(uint32_t*)&h01; hi[1] = *(uint32_t*)&h23;
    lo[0] = *(uint32_t*)&l01; lo[1] = *(uint32_t*)&l23;
}

__device__ __forceinline__ void splitp(float x, float y, uint32_t& hi, uint32_t& lo)
{
    __nv_bfloat16 hx = __float2bfloat16_rn(x);
    __nv_bfloat16 hy = __float2bfloat16_rn(y);
    __nv_bfloat16 lx = __float2bfloat16_rn(x - __bfloat162float(hx));
    __nv_bfloat16 ly = __float2bfloat16_rn(y - __bfloat162float(hy));
    __nv_bfloat162 hh; hh.x = hx; hh.y = hy;
    __nv_bfloat162 ll; ll.x = lx; ll.y = ly;
    hi = *(uint32_t*)&hh; lo = *(uint32_t*)&ll;
}

__device__ __forceinline__ uint32_t packh2(float x, float y)
{
    __half2 h = __floats2half2_rn(x, y);
    return *(uint32_t*)&h;
}

// ---------------------------------------------------------------------------
// Conversion kernels
// ---------------------------------------------------------------------------
__global__ void convert_split(const float* __restrict__ src,
                              bf16* __restrict__ hi, bf16* __restrict__ lo,
                              int n4)
{
    int i = blockIdx.x * blockDim.x + threadIdx.x;
    if (i >= n4) return;
    float4 v = ((const float4*)src)[i];
    uint32_t h[2], l[2];
    split4(v, h, l);
    ((uint2*)hi)[i] = make_uint2(h[0], h[1]);
    ((uint2*)lo)[i] = make_uint2(l[0], l[1]);
}

__global__ void convert_f16(const float* __restrict__ src,
                            __half* __restrict__ dst, int n4)
{
    int i = blockIdx.x * blockDim.x + threadIdx.x;
    if (i >= n4) return;
    float4 v = ((const float4*)src)[i];
    ((uint2*)dst)[i] = make_uint2(packh2(v.x, v.y), packh2(v.z, v.w));
}

// ===========================================================================
// QKV GEMM NT on bf16 hi/lo, 3-pass. CTA 128x128, K-chunk 32, 2-stage
// cp.async, ldmatrix, 2 CTAs/SM. q,k cols -> bf16 hi/lo; v cols -> fp16.
// ===========================================================================
#define G_ARR 10240                  // 128*40*2 bytes
#define G_STAGE (4 * G_ARR)          // 40960
#define G_SMEM (2 * G_STAGE)         // 81920
#define NCHUNK (KDIM / 32)

__global__ __launch_bounds__(256, 2) void gemm_qkv(
    const bf16* __restrict__ Agh, const bf16* __restrict__ Agl,
    const bf16* __restrict__ Bgh, const bf16* __restrict__ Bgl,
    bf16* __restrict__ Ch, bf16* __restrict__ Cl,
    __half* __restrict__ Cv, int N)
{
    extern __shared__ char gsm[];
    const uint32_t sb0 = smem_u32(gsm);

    const int tid = threadIdx.x;
    const int wid = tid >> 5;
    const int lid = tid & 31;
    const int g   = lid >> 2;
    const int tig = lid & 3;
    const int wm  = wid & 1;
    const int wn  = wid >> 1;
    const int bY  = blockIdx.y * 128;
    const int bX  = blockIdx.x * 128;

    const uint32_t aOff = (uint32_t)(wm * 64 + (lid & 15)) * 80
                        + ((lid & 16) ? 16u : 0u);
    const uint32_t bOff = (uint32_t)(wn * 32 + (lid & 7) + ((lid & 16) ? 8 : 0)) * 80
                        + ((lid & 8) ? 16u : 0u);

    const int ldRow = tid >> 2;
    const int ldCh  = tid & 3;
#define G_LOAD(c, st) do {                                                     \
        const uint32_t sb_ = sb0 + (st) * G_STAGE;                             \
        _Pragma("unroll")                                                      \
        for (int j_ = 0; j_ < 2; j_++) {                                       \
            const int row_ = ldRow + 64 * j_;                                  \
            const uint32_t d_ = (uint32_t)row_ * 80 + ldCh * 16;               \
            const size_t ao_ = (size_t)(bY + row_) * KDIM + (c) * 32 + ldCh * 8;\
            const size_t bo_ = (size_t)(bX + row_) * KDIM + (c) * 32 + ldCh * 8;\
            cp16(sb_ + d_,             Agh + ao_);                             \
            cp16(sb_ + G_ARR + d_,     Agl + ao_);                             \
            cp16(sb_ + 2 * G_ARR + d_, Bgh + bo_);                             \
            cp16(sb_ + 3 * G_ARR + d_, Bgl + bo_);                             \
        }                                                                      \
    } while (0)

    float acc[4][4][4];
#pragma unroll
    for (int mi = 0; mi < 4; mi++)
#pragma unroll
        for (int ni = 0; ni < 4; ni++)
#pragma unroll
            for (int r = 0; r < 4; r++) acc[mi][ni][r] = 0.f;

    G_LOAD(0, 0); CP_COMMIT();
    G_LOAD(1, 1); CP_COMMIT();

    for (int c = 0; c < NCHUNK; c++) {
        if (c + 1 < NCHUNK) { CP_WAIT1(); } else { CP_WAIT0(); }
        __syncthreads();

        const uint32_t sb = sb0 + (c & 1) * G_STAGE;
#pragma unroll
        for (int k16 = 0; k16 < 2; k16++) {
            const uint32_t kb = k16 * 32;
#pragma unroll
            for (int p = 0; p < 3; p++) {
                const uint32_t aBase = sb + ((p < 2) ? 0 : G_ARR) + aOff + kb;
                const uint32_t bBase = sb + ((p == 1) ? 3 * G_ARR : 2 * G_ARR)
                                       + bOff + kb;
                uint32_t bf_[2][4];
                ldsm4(bf_[0][0], bf_[0][1], bf_[0][2], bf_[0][3], bBase);
                ldsm4(bf_[1][0], bf_[1][1], bf_[1][2], bf_[1][3], bBase + 16 * 80);
#pragma unroll
                for (int mi = 0; mi < 4; mi++) {
                    uint32_t a0, a1, a2, a3;
                    ldsm4(a0, a1, a2, a3, aBase + (uint32_t)mi * 16 * 80);
#pragma unroll
                    for (int ni = 0; ni < 4; ni++)
                        mma_bf16(acc[mi][ni], a0, a1, a2, a3,
                                 bf_[ni >> 1][(ni & 1) * 2],
                                 bf_[ni >> 1][(ni & 1) * 2 + 1]);
                }
            }
        }
        __syncthreads();
        if (c + 2 < NCHUNK) { G_LOAD(c + 2, (c & 1)); CP_COMMIT(); }
    }

    // epilogue: q,k -> bf16 hi/lo at stride N; v -> fp16 at stride DD
    const bool isV = (bX >= 2 * DD);
#pragma unroll
    for (int mi = 0; mi < 4; mi++) {
        const int r0 = bY + wm * 64 + mi * 16 + g;
#pragma unroll
        for (int ni = 0; ni < 4; ni++) {
            const int c0 = bX + wn * 32 + ni * 8 + tig * 2;
            if (isV) {
                const int cv = c0 - 2 * DD;
                *(uint32_t*)&Cv[(size_t)r0 * DD + cv] =
                    packh2(acc[mi][ni][0], acc[mi][ni][1]);
                *(uint32_t*)&Cv[(size_t)(r0 + 8) * DD + cv] =
                    packh2(acc[mi][ni][2], acc[mi][ni][3]);
            } else {
                uint32_t hp, lp;
                splitp(acc[mi][ni][0], acc[mi][ni][1], hp, lp);
                *(uint32_t*)&Ch[(size_t)r0 * N + c0] = hp;
                *(uint32_t*)&Cl[(size_t)r0 * N + c0] = lp;
                splitp(acc[mi][ni][2], acc[mi][ni][3], hp, lp);
                *(uint32_t*)&Ch[(size_t)(r0 + 8) * N + c0] = hp;
                *(uint32_t*)&Cl[(size_t)(r0 + 8) * N + c0] = lp;
            }
        }
    }
#undef G_LOAD
}

// ===========================================================================
// Flash attention: S = QK^T bf16 3-pass (accurate scores), PV fp16 1-pass.
// CTA: 128 q-rows of one (b,h); 8 warps x 16-row strips; KV tiles 64;
// 2-stage cp.async. V fp16 natural [kv][hd]; PV B-frags via ldmatrix.trans.
// z written fp16. smem: Qh/Ql[128][72]bf16 + 2 x (Kh,Kl bf16 + V16 f16)[64][72].
// ===========================================================================
#define F_QARR 18432                 // 128*72*2
#define F_KARR 9216                  // 64*72*2
#define F_STAGE (3 * F_KARR)         // 27648
#define F_SMEM (2 * F_QARR + 2 * F_STAGE)   // 92160

__global__ __launch_bounds__(256, 1) void flash_pc(
    const bf16* __restrict__ qh, const bf16* __restrict__ ql,
    const __half* __restrict__ v16, __half* __restrict__ z16)
{
    extern __shared__ char fsmc[];
    const uint32_t sb  = smem_u32(fsmc);
    const uint32_t sQh = sb;
    const uint32_t sQl = sb + F_QARR;
    const uint32_t sKV = sb + 2 * F_QARR;

    const int qt  = (TT / 128 - 1) - blockIdx.x;   // heavy tiles first
    const int h   = blockIdx.y;
    const int b   = blockIdx.z;
    const int tid = threadIdx.x;
    const int wid = tid >> 5;
    const int lid = tid & 31;
    const int g   = lid >> 2;
    const int tig = lid & 3;
    const int q0  = qt * 128;
    const int nkv = 2 * qt + 2;
    const int qwmin = q0 + wid * 16;

    // Q cp.async
#pragma unroll
    for (int j = 0; j < 4; j++) {
        const int idx = tid + 256 * j;
        const int row = idx >> 3;
        const int ch  = idx & 7;
        const size_t off = (size_t)(b * TT + q0 + row) * QKV_N + h * HD + ch * 8;
        const uint32_t d = (uint32_t)row * 144 + ch * 16;
        cp16(sQh + d, qh + off);
        cp16(sQl + d, ql + off);
    }

#define F_LOADKV(kt, st) do {                                                  \
        const uint32_t kb_ = sKV + (st) * F_STAGE;                             \
        _Pragma("unroll")                                                      \
        for (int j_ = 0; j_ < 2; j_++) {                                       \
            const int idx_ = tid + 256 * j_;                                   \
            const int row_ = idx_ >> 3;                                        \
            const int ch_  = idx_ & 7;                                         \
            const size_t bk_ = (size_t)(b * TT + (kt) * 64 + row_) * QKV_N     \
                             + DD + h * HD + ch_ * 8;                          \
            const size_t bv_ = (size_t)(b * TT + (kt) * 64 + row_) * DD        \
                             + h * HD + ch_ * 8;                               \
            const uint32_t d_ = (uint32_t)row_ * 144 + ch_ * 16;               \
            cp16(kb_ + d_,              qh  + bk_);                            \
            cp16(kb_ + F_KARR + d_,     ql  + bk_);                            \
            cp16(kb_ + 2 * F_KARR + d_, v16 + bv_);                            \
        }                                                                      \
    } while (0)

    F_LOADKV(0, 0); CP_COMMIT();
    F_LOADKV(1, 1); CP_COMMIT();

    const uint32_t qOff = (uint32_t)(wid * 16 + (lid & 15)) * 144
                        + ((lid & 16) ? 16u : 0u);
    const uint32_t kOff = (uint32_t)((lid & 7) + ((lid & 16) ? 8 : 0)) * 144
                        + ((lid & 8) ? 16u : 0u);
    const uint32_t vRow = (uint32_t)((lid & 7) + ((lid & 8) ? 8 : 0)) * 144
                        + ((lid & 16) ? 16u : 0u);

    float m_[2], l_[2], o_[8][4];
    m_[0] = m_[1] = -1e30f;
    l_[0] = l_[1] = 0.f;
#pragma unroll
    for (int ni = 0; ni < 8; ni++)
#pragma unroll
        for (int e = 0; e < 4; e++) o_[ni][e] = 0.f;

    for (int kt = 0; kt < nkv; kt++) {
        if (kt + 1 < nkv) { CP_WAIT1(); } else { CP_WAIT0(); }
        __syncthreads();

        const uint32_t st  = sKV + (kt & 1) * F_STAGE;
        const uint32_t sKh = st, sKl = st + F_KARR;
        const uint32_t sV  = st + 2 * F_KARR;

        if (kt * 64 <= qwmin + 15) {
            // ---- S = Q K^T (bf16 3-pass) ----
            float s[8][4];
#pragma unroll
            for (int ni = 0; ni < 8; ni++)
#pragma unroll
                for (int e = 0; e < 4; e++) s[ni][e] = 0.f;

#pragma unroll
            for (int k16 = 0; k16 < 4; k16++) {
                const uint32_t kb = k16 * 32;
                uint32_t qh0, qh1, qh2, qh3, ql0, ql1, ql2, ql3;
                ldsm4(qh0, qh1, qh2, qh3, sQh + qOff + kb);
                ldsm4(ql0, ql1, ql2, ql3, sQl + qOff + kb);
                uint32_t bh[4][4], bl[4][4];
#pragma unroll
                for (int nh = 0; nh < 4; nh++) {
                    const uint32_t ro = (uint32_t)nh * 16 * 144;
                    ldsm4(bh[nh][0], bh[nh][1], bh[nh][2], bh[nh][3],
                          sKh + kOff + ro + kb);
                    ldsm4(bl[nh][0], bl[nh][1], bl[nh][2], bl[nh][3],
                          sKl + kOff + ro + kb);
                }
#pragma unroll
                for (int ni = 0; ni < 8; ni++) {
                    const int nh = ni >> 1, rs = (ni & 1) * 2;
                    mma_bf16(s[ni], qh0, qh1, qh2, qh3, bh[nh][rs], bh[nh][rs + 1]);
                    mma_bf16(s[ni], qh0, qh1, qh2, qh3, bl[nh][rs], bl[nh][rs + 1]);
                    mma_bf16(s[ni], ql0, ql1, ql2, ql3, bh[nh][rs], bh[nh][rs + 1]);
                }
            }

#pragma unroll
            for (int ni = 0; ni < 8; ni++)
#pragma unroll
                for (int e = 0; e < 4; e++) s[ni][e] *= 0.125f;

            if (kt * 64 + 63 > qwmin) {
#pragma unroll
                for (int ni = 0; ni < 8; ni++)
#pragma unroll
                    for (int e = 0; e < 4; e++) {
                        const int qr = qwmin + g + ((e >= 2) ? 8 : 0);
                        const int kc = kt * 64 + ni * 8 + tig * 2 + (e & 1);
                        if (kc > qr) s[ni][e] = -1e30f;
                    }
            }

            // ---- online softmax ----
            float mx0 = s[0][0], mx1 = s[0][2];
#pragma unroll
            for (int ni = 0; ni < 8; ni++) {
                mx0 = fmaxf(mx0, fmaxf(s[ni][0], s[ni][1]));
                mx1 = fmaxf(mx1, fmaxf(s[ni][2], s[ni][3]));
            }
            mx0 = fmaxf(mx0, __shfl_xor_sync(0xffffffffu, mx0, 1));
            mx0 = fmaxf(mx0, __shfl_xor_sync(0xffffffffu, mx0, 2));
            mx1 = fmaxf(mx1, __shfl_xor_sync(0xffffffffu, mx1, 1));
            mx1 = fmaxf(mx1, __shfl_xor_sync(0xffffffffu, mx1, 2));

            const float mn0 = fmaxf(m_[0], mx0);
            const float mn1 = fmaxf(m_[1], mx1);
            const float al0 = __expf(m_[0] - mn0);
            const float al1 = __expf(m_[1] - mn1);

            float ps0 = 0.f, ps1 = 0.f;
#pragma unroll
            for (int ni = 0; ni < 8; ni++) {
                s[ni][0] = __expf(s[ni][0] - mn0); ps0 += s[ni][0];
                s[ni][1] = __expf(s[ni][1] - mn0); ps0 += s[ni][1];
                s[ni][2] = __expf(s[ni][2] - mn1); ps1 += s[ni][2];
                s[ni][3] = __expf(s[ni][3] - mn1); ps1 += s[ni][3];
            }
            ps0 += __shfl_xor_sync(0xffffffffu, ps0, 1);
            ps0 += __shfl_xor_sync(0xffffffffu, ps0, 2);
            ps1 += __shfl_xor_sync(0xffffffffu, ps1, 1);
            ps1 += __shfl_xor_sync(0xffffffffu, ps1, 2);

            l_[0] = l_[0] * al0 + ps0;
            l_[1] = l_[1] * al1 + ps1;
            m_[0] = mn0; m_[1] = mn1;
#pragma unroll
            for (int ni = 0; ni < 8; ni++) {
                o_[ni][0] *= al0; o_[ni][1] *= al0;
                o_[ni][2] *= al1; o_[ni][3] *= al1;
            }

            // ---- O += P V (fp16 single pass) ----
#pragma unroll
            for (int k16 = 0; k16 < 4; k16++) {
                const int n0 = 2 * k16, n1 = 2 * k16 + 1;
                const uint32_t p0 = packh2(s[n0][0], s[n0][1]);
                const uint32_t p1 = packh2(s[n0][2], s[n0][3]);
                const uint32_t p2 = packh2(s[n1][0], s[n1][1]);
                const uint32_t p3 = packh2(s[n1][2], s[n1][3]);

                const uint32_t rb = (uint32_t)k16 * 16 * 144;
                uint32_t vh[4][4];
#pragma unroll
                for (int nh = 0; nh < 4; nh++)
                    ldsm4t(vh[nh][0], vh[nh][1], vh[nh][2], vh[nh][3],
                           sV + vRow + rb + (uint32_t)nh * 32);
#pragma unroll
                for (int ni = 0; ni < 8; ni++) {
                    const int nh = ni >> 1, rs = (ni & 1) * 2;
                    mma_f16(o_[ni], p0, p1, p2, p3, vh[nh][rs], vh[nh][rs + 1]);
                }
            }
        }

        __syncthreads();
        if (kt + 2 < nkv) { F_LOADKV(kt + 2, (kt & 1)); CP_COMMIT(); }
    }

    // epilogue: normalize, write z fp16
    const float il0 = 1.f / l_[0];
    const float il1 = 1.f / l_[1];
    const size_t r0 = (size_t)(b * TT + q0 + wid * 16 + g);
#pragma unroll
    for (int ni = 0; ni < 8; ni++) {
        const int col = h * HD + ni * 8 + tig * 2;
        *(uint32_t*)&z16[r0 * DD + col] =
            packh2(o_[ni][0] * il0, o_[ni][1] * il0);
        *(uint32_t*)&z16[(r0 + 8) * DD + col] =
            packh2(o_[ni][2] * il1, o_[ni][3] * il1);
    }
#undef F_LOADKV
}

// ===========================================================================
// Out-proj GEMM NT, fp16 single-pass: out = z16 * Wo16^T, fp32 out.
// CTA 128x128, K-chunk 64, 2-stage cp.async, 2 CTAs/SM.
// smem per stage: A16,B16 [128][72] fp16 (144B stride).
// ===========================================================================
#define H_ARR 18432                  // 128*72*2
#define H_STAGE (2 * H_ARR)          // 36864
#define H_SMEM (2 * H_STAGE)         // 73728
#define H_NCHUNK (KDIM / 64)         // 16

__global__ __launch_bounds__(256, 2) void gemm_f16(
    const __half* __restrict__ Ag, const __half* __restrict__ Bg,
    float* __restrict__ Cf, int N)
{
    extern __shared__ char hsm[];
    const uint32_t sb0 = smem_u32(hsm);

    const int tid = threadIdx.x;
    const int wid = tid >> 5;
    const int lid = tid & 31;
    const int g   = lid >> 2;
    const int tig = lid & 3;
    const int wm  = wid & 1;
    const int wn  = wid >> 1;
    const int bY  = blockIdx.y * 128;
    const int bX  = blockIdx.x * 128;

    const uint32_t aOff = (uint32_t)(wm * 64 + (lid & 15)) * 144
                        + ((lid & 16) ? 16u : 0u);
    const uint32_t bOff = (uint32_t)(wn * 32 + (lid & 7) + ((lid & 16) ? 8 : 0)) * 144
                        + ((lid & 8) ? 16u : 0u);

#define H_LOAD(c, st) do {                                                     \
        const uint32_t sb_ = sb0 + (st) * H_STAGE;                             \
        _Pragma("unroll")                                                      \
        for (int j_ = 0; j_ < 4; j_++) {                                       \
            const int idx_ = tid + 256 * j_;                                   \
            const int row_ = idx_ >> 3;                                        \
            const int ch_  = idx_ & 7;                                         \
            const uint32_t d_ = (uint32_t)row_ * 144 + ch_ * 16;               \
            cp16(sb_ + d_,         Ag + (size_t)(bY + row_) * KDIM + (c) * 64 + ch_ * 8); \
            cp16(sb_ + H_ARR + d_, Bg + (size_t)(bX + row_) * KDIM + (c) * 64 + ch_ * 8); \
        }                                                                      \
    } while (0)

    float acc[4][4][4];
#pragma unroll
    for (int mi = 0; mi < 4; mi++)
#pragma unroll
        for (int ni = 0; ni < 4; ni++)
#pragma unroll
            for (int r = 0; r < 4; r++) acc[mi][ni][r] = 0.f;

    H_LOAD(0, 0); CP_COMMIT();
    H_LOAD(1, 1); CP_COMMIT();

    for (int c = 0; c < H_NCHUNK; c++) {
        if (c + 1 < H_NCHUNK) { CP_WAIT1(); } else { CP_WAIT0(); }
        __syncthreads();

        const uint32_t sb = sb0 + (c & 1) * H_STAGE;
#pragma unroll
        for (int k16 = 0; k16 < 4; k16++) {
            const uint32_t kb = k16 * 32;
            const uint32_t bBase = sb + H_ARR + bOff + kb;
            uint32_t bf_[2][4];
            ldsm4(bf_[0][0], bf_[0][1], bf_[0][2], bf_[0][3], bBase);
            ldsm4(bf_[1][0], bf_[1][1], bf_[1][2], bf_[1][3], bBase + 16 * 144);
#pragma unroll
            for (int mi = 0; mi < 4; mi++) {
                uint32_t a0, a1, a2, a3;
                ldsm4(a0, a1, a2, a3, sb + aOff + kb + (uint32_t)mi * 16 * 144);
#pragma unroll
                for (int ni = 0; ni < 4; ni++)
                    mma_f16(acc[mi][ni], a0, a1, a2, a3,
                            bf_[ni >> 1][(ni & 1) * 2],
                            bf_[ni >> 1][(ni & 1) * 2 + 1]);
            }
        }
        __syncthreads();
        if (c + 2 < H_NCHUNK) { H_LOAD(c + 2, (c & 1)); CP_COMMIT(); }
    }

#pragma unroll
    for (int mi = 0; mi < 4; mi++) {
        const int r0 = bY + wm * 64 + mi * 16 + g;
#pragma unroll
        for (int ni = 0; ni < 4; ni++) {
            const int c0 = bX + wn * 32 + ni * 8 + tig * 2;
            float2 v0; v0.x = acc[mi][ni][0]; v0.y = acc[mi][ni][1];
            float2 v1; v1.x = acc[mi][ni][2]; v1.y = acc[mi][ni][3];
            *(float2*)(Cf + (size_t)r0 * N + c0)       = v0;
            *(float2*)(Cf + (size_t)(r0 + 8) * N + c0) = v1;
        }
    }
#undef H_LOAD
}

// ---------------------------------------------------------------------------
extern "C" void kernel_launch(void* const* d_in, const int* in_sizes, int n_in,
                              void* d_out, int out_size)
{
    const float* X    = (const float*)d_in[0];
    const float* Wqkv = (const float*)d_in[1];
    const float* Wout = (const float*)d_in[2];
    float* out = (float*)d_out;

    bf16 *Xh, *Xl, *Wqh, *Wql, *qh, *ql;
    __half *Wo16, *v16, *z16;
    cudaGetSymbolAddress((void**)&Xh,   g_Xh);
    cudaGetSymbolAddress((void**)&Xl,   g_Xl);
    cudaGetSymbolAddress((void**)&Wqh,  g_Wqh);
    cudaGetSymbolAddress((void**)&Wql,  g_Wql);
    cudaGetSymbolAddress((void**)&Wo16, g_Wo16);
    cudaGetSymbolAddress((void**)&qh,   g_qh);
    cudaGetSymbolAddress((void**)&ql,   g_ql);
    cudaGetSymbolAddress((void**)&v16,  g_v16);
    cudaGetSymbolAddress((void**)&z16,  g_z16);

    cudaFuncSetAttribute(gemm_qkv,
                         cudaFuncAttributeMaxDynamicSharedMemorySize, G_SMEM);
    cudaFuncSetAttribute(flash_pc,
                         cudaFuncAttributeMaxDynamicSharedMemorySize, F_SMEM);
    cudaFuncSetAttribute(gemm_f16,
                         cudaFuncAttributeMaxDynamicSharedMemorySize, H_SMEM);

    // 0) input conversions
    convert_split<<<M_ROWS * KDIM / 1024, 256>>>(X, Xh, Xl, M_ROWS * KDIM / 4);
    convert_split<<<QKV_N * KDIM / 1024, 256>>>(Wqkv, Wqh, Wql, QKV_N * KDIM / 4);
    convert_f16<<<DD * DD / 1024, 256>>>(Wout, Wo16, DD * DD / 4);

    // 1) qkv = X @ Wqkv^T  (bf16x3): q,k -> bf16 hi/lo, v -> fp16
    gemm_qkv<<<dim3(QKV_N / 128, M_ROWS / 128), 256, G_SMEM>>>(
        Xh, Xl, Wqh, Wql, qh, ql, v16, QKV_N);

    // 2) causal flash attention -> z fp16 (S bf16x3, PV fp16x1)
    flash_pc<<<dim3(TT / 128, HH, BB), 256, F_SMEM>>>(qh, ql, v16, z16);

    // 3) out = z16 @ Wo16^T  (fp16x1) -> fp32
    gemm_f16<<<dim3(DD / 128, M_ROWS / 128), 256, H_SMEM>>>(z16, Wo16, out, DD);
}